// round 6
// baseline (speedup 1.0000x reference)
#include <cuda_runtime.h>

#define THREADS 128
#define GPB 16            // graphs per block (8 lane-groups x 2 graphs/thread)

// Output layout: concat of recon[B,4,13,13], mu[B,13,16], logvar[B,13,16] (fp32)
#define R_MU 22151168ull
#define R_LV 28966912ull

typedef unsigned long long u64;

__device__ __forceinline__ void ffma2(u64 &d, u64 a, u64 b) {
    asm("fma.rn.f32x2 %0, %1, %2, %0;" : "+l"(d) : "l"(a), "l"(b));
}
__device__ __forceinline__ u64 pack2(float lo, float hi) {
    u64 r; asm("mov.b64 %0, {%1, %2};" : "=l"(r) : "f"(lo), "f"(hi)); return r;
}
__device__ __forceinline__ float2 unpack2(u64 v) {
    float2 r; asm("mov.b64 {%0, %1}, %2;" : "=f"(r.x), "=f"(r.y) : "l"(v)); return r;
}
__device__ __forceinline__ float leaky(float v) { return v >= 0.f ? v : 0.01f * v; }
__device__ __forceinline__ u64 plo(float4 w) { return pack2(w.x, w.y); }
__device__ __forceinline__ u64 phi(float4 w) { return pack2(w.z, w.w); }

// 16-wide dot with 2 accumulator chains
__device__ __forceinline__ float dot16s(const u64* pw, const u64* a2) {
    u64 accA = 0ull, accB = 0ull;
#pragma unroll
    for (int q = 0; q < 4; q++) ffma2(accA, a2[q],     pw[q]);
#pragma unroll
    for (int q = 0; q < 4; q++) ffma2(accB, a2[q + 4], pw[q + 4]);
    float2 fa = unpack2(accA), fb = unpack2(accB);
    return (fa.x + fb.x) + (fa.y + fb.y);
}

#define ADJ_PITCH 14
#define ADJ_G     728            // 4*13*14 floats per graph

struct __align__(16) Smem {
    float4 w0v[256], w1v[256], decv[256];  // 12288 B
    float4 xsv[GPB * 65];                  // 16640 B (pitch 5 float4 per node row)
    float  adjP[GPB * ADJ_G];              // 46592 B; reused as recon staging
    float  eps1p[4];
    float  b0[64], b1[64], decb[64], fc1b[16], fc2b[16];
};

__global__ __launch_bounds__(THREADS, 3) void vae_fused(
    const float* __restrict__ adj,
    const float* __restrict__ init_weight,
    const float* __restrict__ eps_param,
    const float* __restrict__ mlp_w0,  const float* __restrict__ mlp_b0,
    const float* __restrict__ mlp_w1,  const float* __restrict__ mlp_b1,
    const float* __restrict__ bn_in_gamma,  const float* __restrict__ bn_in_beta,
    const float* __restrict__ bn_in_mean,   const float* __restrict__ bn_in_var,
    const float* __restrict__ bn_out_gamma, const float* __restrict__ bn_out_beta,
    const float* __restrict__ bn_out_mean,  const float* __restrict__ bn_out_var,
    const float* __restrict__ fc1_w, const float* __restrict__ fc1_b,
    const float* __restrict__ fc2_w, const float* __restrict__ fc2_b,
    const float* __restrict__ dec_w, const float* __restrict__ dec_b,
    float* __restrict__ out)
{
    extern __shared__ Smem sm[];
    Smem& s = sm[0];
    const int tid = threadIdx.x;

    if (tid < 4) s.eps1p[tid] = 1.f + eps_param[tid];
    for (int i = tid; i < 256; i += THREADS) {
        s.w0v[i]  = ((const float4*)mlp_w0)[i];
        s.w1v[i]  = ((const float4*)mlp_w1)[i];
        s.decv[i] = ((const float4*)dec_w)[i];
    }
    for (int i = tid; i < 64; i += THREADS) {
        s.b0[i] = mlp_b0[i]; s.b1[i] = mlp_b1[i]; s.decb[i] = dec_b[i];
    }
    if (tid < 16) { s.fc1b[tid] = fc1_b[tid]; s.fc2b[tid] = fc2_b[tid]; }

    {   // stage adj into pitch-14 layout: adjP[g][(i*13+n)*14 + m]
        const float* asrc = adj + (size_t)blockIdx.x * (GPB * 676);
        for (int idx = tid; idx < GPB * 676; idx += THREADS) {
            int g  = idx / 676;
            int r  = idx - g * 676;
            int in = r / 13;            // i*13+n
            int m  = r - in * 13;
            s.adjP[g * ADJ_G + in * ADJ_PITCH + m] = asrc[idx];
        }
    }
    __syncthreads();

    const int grp = tid >> 4;          // 0..7
    const int n   = tid & 15;          // node; lanes 13..15 idle for compute
    const int g0  = grp * 2;
    const size_t b0g = (size_t)blockIdx.x * GPB + g0;
    const float* adB[2] = { s.adjP + g0 * ADJ_G, s.adjP + (g0 + 1) * ADJ_G };
    float4*      xp[2]  = { s.xsv + g0 * 65,     s.xsv + (g0 + 1) * 65 };
    const bool act = (n < 13);
    const int nn = act ? n : 0;

    float x[2][16];

    // ---- init: x[n,:] = sum_m (sum_i adj[i,n,m]) * W[m,:]
    if (act) {
        float as[2][13];
#pragma unroll
        for (int g = 0; g < 2; g++) {
            const float* ab = adB[g] + n * ADJ_PITCH;
#pragma unroll
            for (int mp = 0; mp < 6; mp++) {
                float2 v0 = *(const float2*)(ab + 2*mp);
                float2 v1 = *(const float2*)(ab + 182 + 2*mp);
                float2 v2 = *(const float2*)(ab + 364 + 2*mp);
                float2 v3 = *(const float2*)(ab + 546 + 2*mp);
                as[g][2*mp]   = v0.x + v1.x + v2.x + v3.x;
                as[g][2*mp+1] = v0.y + v1.y + v2.y + v3.y;
            }
            as[g][12] = ab[12] + ab[182+12] + ab[364+12] + ab[546+12];
        }
        u64 x2[2][8];
#pragma unroll
        for (int g = 0; g < 2; g++)
#pragma unroll
            for (int q = 0; q < 8; q++) x2[g][q] = 0ull;
#pragma unroll
        for (int m = 0; m < 13; m++) {
            const float4* wr = (const float4*)init_weight + m * 4;
            float4 w0_ = __ldg(wr), w1_ = __ldg(wr+1), w2_ = __ldg(wr+2), w3_ = __ldg(wr+3);
            u64 pw[8] = { plo(w0_), phi(w0_), plo(w1_), phi(w1_),
                          plo(w2_), phi(w2_), plo(w3_), phi(w3_) };
#pragma unroll
            for (int g = 0; g < 2; g++) {
                u64 a = pack2(as[g][m], as[g][m]);
#pragma unroll
                for (int q = 0; q < 8; q++) ffma2(x2[g][q], a, pw[q]);
            }
        }
#pragma unroll
        for (int g = 0; g < 2; g++) {
#pragma unroll
            for (int q = 0; q < 8; q++) { float2 f = unpack2(x2[g][q]); x[g][2*q] = f.x; x[g][2*q+1] = f.y; }
#pragma unroll
            for (int q = 0; q < 4; q++)
                xp[g][n*5 + q] = make_float4(x[g][4*q], x[g][4*q+1], x[g][4*q+2], x[g][4*q+3]);
        }
    }
    __syncwarp();

    // ---- 4 GIN layers ----
#pragma unroll 1
    for (int l = 0; l < 4; l++) {
        const int pi = l * 13 + nn;
        const float si = bn_in_gamma[pi]  * rsqrtf(bn_in_var[pi]  + 1e-5f);
        const float ti = bn_in_beta[pi]   - bn_in_mean[pi]  * si;
        const float so = bn_out_gamma[pi] * rsqrtf(bn_out_var[pi] + 1e-5f);
        const float to = bn_out_beta[pi]  - bn_out_mean[pi] * so;
        if (act) {
            const float ep = s.eps1p[l];
            u64 agg2[2][8];
#pragma unroll
            for (int g = 0; g < 2; g++)
#pragma unroll
                for (int q = 0; q < 8; q++) agg2[g][q] = pack2(ep * x[g][2*q], ep * x[g][2*q+1]);
#pragma unroll
            for (int i = 0; i < 4; i++) {
#pragma unroll
                for (int g = 0; g < 2; g++) {
                    const float* ab = adB[g] + (i*13 + n) * ADJ_PITCH;
#pragma unroll
                    for (int mp = 0; mp < 6; mp++) {
                        float2 av = *(const float2*)(ab + 2*mp);
                        float4 xr0 = xp[g][(2*mp)*5 + i];
                        float4 xr1 = xp[g][(2*mp+1)*5 + i];
                        u64 a0 = pack2(av.x, av.x);
                        u64 a1 = pack2(av.y, av.y);
                        ffma2(agg2[g][2*i],     a0, plo(xr0));
                        ffma2(agg2[g][2*i + 1], a0, phi(xr0));
                        ffma2(agg2[g][2*i],     a1, plo(xr1));
                        ffma2(agg2[g][2*i + 1], a1, phi(xr1));
                    }
                    float a12 = ab[12];
                    float4 xr = xp[g][12*5 + i];
                    u64 a = pack2(a12, a12);
                    ffma2(agg2[g][2*i],     a, plo(xr));
                    ffma2(agg2[g][2*i + 1], a, phi(xr));
                }
            }
            const float4* w0b = s.w0v + l*64;
            const float*  bb0 = s.b0 + l*16;
            float h1[2][16];
#pragma unroll
            for (int e = 0; e < 16; e++) {
                const float4* wr = w0b + e*4;
                float4 wa = wr[0], wb = wr[1], wc = wr[2], wd = wr[3];
                u64 pw[8] = { plo(wa), phi(wa), plo(wb), phi(wb),
                              plo(wc), phi(wc), plo(wd), phi(wd) };
#pragma unroll
                for (int g = 0; g < 2; g++)
                    h1[g][e] = leaky(si * (dot16s(pw, agg2[g]) + bb0[e]) + ti);
            }
            u64 h2[2][8];
#pragma unroll
            for (int g = 0; g < 2; g++)
#pragma unroll
                for (int q = 0; q < 8; q++) h2[g][q] = pack2(h1[g][2*q], h1[g][2*q+1]);
            const float4* w1b = s.w1v + l*64;
            const float*  bb1 = s.b1 + l*16;
#pragma unroll
            for (int e = 0; e < 16; e++) {
                const float4* wr = w1b + e*4;
                float4 wa = wr[0], wb = wr[1], wc = wr[2], wd = wr[3];
                u64 pw[8] = { plo(wa), phi(wa), plo(wb), phi(wb),
                              plo(wc), phi(wc), plo(wd), phi(wd) };
#pragma unroll
                for (int g = 0; g < 2; g++)
                    x[g][e] = leaky(so * (dot16s(pw, h2[g]) + bb1[e]) + to);
            }
        }
        __syncwarp();
        if (act) {
#pragma unroll
            for (int g = 0; g < 2; g++)
#pragma unroll
                for (int q = 0; q < 4; q++)
                    xp[g][n*5 + q] = make_float4(x[g][4*q], x[g][4*q+1], x[g][4*q+2], x[g][4*q+3]);
        }
        __syncwarp();
    }

    // ---- heads: mu / logvar ----
    float mu[2][16];
    {
        float lv[2][16];
        if (act) {
            u64 x2[2][8];
#pragma unroll
            for (int g = 0; g < 2; g++)
#pragma unroll
                for (int q = 0; q < 8; q++) x2[g][q] = pack2(x[g][2*q], x[g][2*q+1]);
#pragma unroll
            for (int e = 0; e < 16; e++) {
                const float4* r1 = (const float4*)fc1_w + e*4;
                const float4* r2 = (const float4*)fc2_w + e*4;
                float4 a1 = __ldg(r1), b1_ = __ldg(r1+1), c1 = __ldg(r1+2), d1 = __ldg(r1+3);
                float4 a2 = __ldg(r2), b2_ = __ldg(r2+1), c2 = __ldg(r2+2), d2 = __ldg(r2+3);
                u64 p1[8] = { plo(a1), phi(a1), plo(b1_), phi(b1_), plo(c1), phi(c1), plo(d1), phi(d1) };
                u64 p2[8] = { plo(a2), phi(a2), plo(b2_), phi(b2_), plo(c2), phi(c2), plo(d2), phi(d2) };
#pragma unroll
                for (int g = 0; g < 2; g++) {
                    mu[g][e] = dot16s(p1, x2[g]) + s.fc1b[e];
                    lv[g][e] = dot16s(p2, x2[g]) + s.fc2b[e];
                }
            }
        }
        __syncwarp();
        if (act) {
#pragma unroll
            for (int g = 0; g < 2; g++)
#pragma unroll
                for (int q = 0; q < 4; q++)
                    xp[g][n*5 + q] = make_float4(lv[g][4*q], lv[g][4*q+1], lv[g][4*q+2], lv[g][4*q+3]);
        }
        __syncwarp();
#pragma unroll
        for (int g = 0; g < 2; g++) {
            float4* o4 = (float4*)(out + R_LV + (b0g + g) * 208);
#pragma unroll
            for (int it = 0; it < 4; it++) {
                int idx = it * 16 + n;
                if (idx < 52) o4[idx] = xp[g][(idx >> 2) * 5 + (idx & 3)];
            }
        }
        __syncwarp();
        if (act) {
#pragma unroll
            for (int g = 0; g < 2; g++)
#pragma unroll
                for (int q = 0; q < 4; q++)
                    xp[g][n*5 + q] = make_float4(mu[g][4*q], mu[g][4*q+1], mu[g][4*q+2], mu[g][4*q+3]);
        }
        __syncwarp();
#pragma unroll
        for (int g = 0; g < 2; g++) {
            float4* o4 = (float4*)(out + R_MU + (b0g + g) * 208);
#pragma unroll
            for (int it = 0; it < 4; it++) {
                int idx = it * 16 + n;
                if (idx < 52) o4[idx] = xp[g][(idx >> 2) * 5 + (idx & 3)];
            }
        }
    }

    // ---- decoder: recon staged into the (dead) adjP slice, then coalesced out ----
    u64 mu2[2][8];
    if (act) {
#pragma unroll
        for (int g = 0; g < 2; g++)
#pragma unroll
            for (int q = 0; q < 8; q++) mu2[g][q] = pack2(mu[g][2*q], mu[g][2*q+1]);
    }
    float* rec[2] = { (float*)adB[0], (float*)adB[1] };   // >= 676 floats each, 16B-aligned

#pragma unroll 1
    for (int k = 0; k < 4; k++) {
        __syncwarp();
        float t[2][16];
        if (act) {
            const float4* dwb = s.decv + k*64;
            const float*  dbb = s.decb + k*16;
#pragma unroll
            for (int d = 0; d < 16; d++) {
                const float4* wr = dwb + d*4;
                float4 wa = wr[0], wb = wr[1], wc = wr[2], wd = wr[3];
                u64 pw[8] = { plo(wa), phi(wa), plo(wb), phi(wb),
                              plo(wc), phi(wc), plo(wd), phi(wd) };
#pragma unroll
                for (int g = 0; g < 2; g++)
                    t[g][d] = dot16s(pw, mu2[g]) + dbb[d];
            }
#pragma unroll
            for (int g = 0; g < 2; g++)
#pragma unroll
                for (int q = 0; q < 4; q++)
                    xp[g][n*5 + q] = make_float4(t[g][4*q], t[g][4*q+1], t[g][4*q+2], t[g][4*q+3]);
        }
        __syncwarp();
        if (act) {
#pragma unroll
            for (int g = 0; g < 2; g++) {
                u64 t2[8];
#pragma unroll
                for (int q = 0; q < 8; q++) t2[q] = pack2(t[g][2*q], t[g][2*q+1]);
                float* rr = rec[g] + k * 169 + n * 13;
#pragma unroll
                for (int m = 0; m < 13; m++) {
                    u64 accA = 0ull, accB = 0ull;
#pragma unroll
                    for (int q = 0; q < 2; q++) {
                        float4 xr = xp[g][m*5 + q];
                        ffma2(accA, t2[2*q],     plo(xr));
                        ffma2(accA, t2[2*q + 1], phi(xr));
                    }
#pragma unroll
                    for (int q = 2; q < 4; q++) {
                        float4 xr = xp[g][m*5 + q];
                        ffma2(accB, t2[2*q],     plo(xr));
                        ffma2(accB, t2[2*q + 1], phi(xr));
                    }
                    float2 fa = unpack2(accA), fb = unpack2(accB);
                    float sv = (fa.x + fb.x) + (fa.y + fb.y);
                    rr[m] = sv > 0.f ? sv : 0.f;
                }
            }
        }
    }
    __syncwarp();
    // coalesced recon writeout: 676 floats = 169 float4 per graph
#pragma unroll
    for (int g = 0; g < 2; g++) {
        const float4* r4 = (const float4*)rec[g];
        float4* o4 = (float4*)(out + (b0g + g) * 676);
#pragma unroll
        for (int it = 0; it < 11; it++) {
            int idx = it * 16 + n;
            if (idx < 169) o4[idx] = r4[idx];
        }
    }
}

extern "C" void kernel_launch(void* const* d_in, const int* in_sizes, int n_in,
                              void* d_out, int out_size) {
    (void)in_sizes; (void)n_in; (void)out_size;
    cudaFuncSetAttribute(vae_fused, cudaFuncAttributeMaxDynamicSharedMemorySize,
                         (int)sizeof(Smem));
    vae_fused<<<32768 / GPB, THREADS, sizeof(Smem)>>>(
        (const float*)d_in[0],  (const float*)d_in[1],  (const float*)d_in[2],
        (const float*)d_in[3],  (const float*)d_in[4],  (const float*)d_in[5],
        (const float*)d_in[6],  (const float*)d_in[7],  (const float*)d_in[8],
        (const float*)d_in[9],  (const float*)d_in[10], (const float*)d_in[11],
        (const float*)d_in[12], (const float*)d_in[13], (const float*)d_in[14],
        (const float*)d_in[15], (const float*)d_in[16], (const float*)d_in[17],
        (const float*)d_in[18], (const float*)d_in[19], (const float*)d_in[20],
        (float*)d_out);
}